// round 14
// baseline (speedup 1.0000x reference)
#include <cuda_runtime.h>
#include <cuda_fp16.h>
#include <cstdint>

#define BATCH 8
#define IN_F 4096
#define OUT_F 12288
#define GS 128
#define NG 32
#define OPW 4          // outputs per warp
#define TPB 32         // one warp per CTA; NO intra-CTA sync anywhere

typedef unsigned long long u64;

__device__ float  g_sx[BATCH * NG];        // per-batch per-group sums of x (fp32, exact)
__device__ __align__(16) __half g_xt[IN_F * BATCH];  // x TRANSPOSED [k][b], fp16 (64 KB)

__device__ __forceinline__ u64 pack2(float lo, float hi) {
    u64 r; asm("mov.b64 %0, {%1, %2};" : "=l"(r) : "f"(lo), "f"(hi)); return r;
}
__device__ __forceinline__ void unpack2(u64 v, float& lo, float& hi) {
    asm("mov.b64 {%0, %1}, %2;" : "=f"(lo), "=f"(hi) : "l"(v));
}
__device__ __forceinline__ u64 fma2(u64 a, u64 b, u64 c) {
    u64 d; asm("fma.rn.f32x2 %0, %1, %2, %3;" : "=l"(d) : "l"(a), "l"(b), "l"(c)); return d;
}
__device__ __forceinline__ u64 mul2(u64 a, u64 b) {
    u64 d; asm("mul.rn.f32x2 %0, %1, %2;" : "=l"(d) : "l"(a), "l"(b)); return d;
}
// weights: streaming, evict-first (protect x in L1)
__device__ __forceinline__ int4 ldg_cs(const int* p) {
    int4 v;
    asm("ld.global.cs.v4.u32 {%0,%1,%2,%3}, [%4];"
        : "=r"(v.x), "=r"(v.y), "=r"(v.z), "=r"(v.w) : "l"(p));
    return v;
}
// x rows (16 B = 8 halves = one k, all 8 batches): keep resident in L1
__device__ __forceinline__ uint4 ldg_xr(const uint4* p) {
    uint4 v;
    asm("ld.global.nc.L1::evict_last.v4.u32 {%0,%1,%2,%3}, [%4];"
        : "=r"(v.x), "=r"(v.y), "=r"(v.z), "=r"(v.w) : "l"(p));
    return v;
}
// scales: streaming
__device__ __forceinline__ float4 ldg_cs4(const float* p) {
    float4 v;
    asm("ld.global.cs.v4.f32 {%0,%1,%2,%3}, [%4];"
        : "=f"(v.x), "=f"(v.y), "=f"(v.z), "=f"(v.w) : "l"(p));
    return v;
}
__device__ __forceinline__ float2 h2f(unsigned u) {
    return __half22float2(*(const __half2*)&u);
}

// ---- prekernel: x -> fp16 transposed [k][b], plus Sx[b][g] group sums ----
__global__ void prep_kernel(const float* __restrict__ x) {
    const int gt   = blockIdx.x * blockDim.x + threadIdx.x;
    const int w    = gt >> 5;            // 0..255 = b*32 + g
    const int lane = gt & 31;
    const int b    = w >> 5, g = w & 31;
    const int k0   = g * GS + lane * 4;

    float4 v = __ldg((const float4*)(x + b * IN_F + k0));

    g_xt[(k0 + 0) * BATCH + b] = __float2half_rn(v.x);
    g_xt[(k0 + 1) * BATCH + b] = __float2half_rn(v.y);
    g_xt[(k0 + 2) * BATCH + b] = __float2half_rn(v.z);
    g_xt[(k0 + 3) * BATCH + b] = __float2half_rn(v.w);

    float s = (v.x + v.y) + (v.z + v.w);
    #pragma unroll
    for (int off = 16; off > 0; off >>= 1)
        s += __shfl_xor_sync(0xffffffffu, s, off);
    if (lane == 0) g_sx[w] = s;
}

// ---- main kernel: one warp per 4 outputs; batch-paired acc; front-batched loads ----
__global__ void __launch_bounds__(TPB, 12)
w4a32_main(const int* __restrict__ qw,
           const float* __restrict__ sc, const float* __restrict__ zr,
           float* __restrict__ out)
{
    __shared__ float bounce[OPW * BATCH];

    const int lane = threadIdx.x;
    const int n0   = blockIdx.x * OPW;
    const int klo  = lane * 4;

    const int* qbase = qw + (long)n0 * IN_F + klo;
    const uint4* xrows = (const uint4*)g_xt;    // one uint4 per k-row (8 halves)

    // weights: register pipeline depth 2 (parity buffers)
    int4 qbuf[2][OPW];
    #pragma unroll
    for (int s = 0; s < 2; ++s)
        #pragma unroll
        for (int o = 0; o < OPW; ++o)
            qbuf[s][o] = ldg_cs(qbase + s * GS + o * IN_F);

    // scales: single buffer, distance 1 (captured before overwrite)
    float4 sv0 = ldg_cs4(sc + n0);

    // x rows: double buffer, distance 1; lane's 4 k-rows are contiguous 64 B
    uint4 xb[2][4];
    #pragma unroll
    for (int k = 0; k < 4; ++k)
        xb[0][k] = ldg_xr(xrows + klo + k);

    // accumulators paired over BATCH: acc[o][bp] = (b=2bp, b=2bp+1)
    u64 acc[OPW][4];
    #pragma unroll
    for (int o = 0; o < OPW; ++o)
        #pragma unroll
        for (int bp = 0; bp < 4; ++bp) acc[o][bp] = 0ull;

    #pragma unroll 2
    for (int g = 0; g < NG; ++g) {
        const int cur = g & 1;

        // capture current operands before refill
        int4 q[OPW];
        #pragma unroll
        for (int o = 0; o < OPW; ++o) q[o] = qbuf[cur][o];
        const float4 sv = sv0;

        // ========== FRONT-BATCHED LOAD BLOCK (9 LDGs, no consumers) ==========
        {   // x rows for group g+1
            const uint4* xr1 = xrows + ((g + 1) & (NG - 1)) * GS + klo;
            #pragma unroll
            for (int k = 0; k < 4; ++k)
                xb[cur ^ 1][k] = ldg_xr(xr1 + k);
        }
        {   // weights for group g+2
            const int gn2 = (g + 2) & (NG - 1);
            #pragma unroll
            for (int o = 0; o < OPW; ++o)
                qbuf[cur][o] = ldg_cs(qbase + gn2 * GS + o * IN_F);
        }
        // scales for group g+1
        sv0 = ldg_cs4(sc + ((g + 1) & (NG - 1)) * OUT_F + n0);
        // =====================================================================

        // convert x rows: xp[k][bp] = fp32 pair (b=2bp, 2bp+1)
        u64 xp[4][4];
        #pragma unroll
        for (int k = 0; k < 4; ++k) {
            const uint4 xv = xb[cur][k];
            float2 f0 = h2f(xv.x), f1 = h2f(xv.y), f2 = h2f(xv.z), f3 = h2f(xv.w);
            xp[k][0] = pack2(f0.x, f0.y);
            xp[k][1] = pack2(f1.x, f1.y);
            xp[k][2] = pack2(f2.x, f2.y);
            xp[k][3] = pack2(f3.x, f3.y);
        }

        // convert weights: qs[o][k] = broadcast pair (s_o*q_ok, s_o*q_ok)
        u64 qs[OPW][4];
        {
            const float sa[OPW] = {sv.x, sv.y, sv.z, sv.w};
            #pragma unroll
            for (int o = 0; o < OPW; ++o) {
                const u64 s2 = pack2(sa[o], sa[o]);
                const float f0 = (float)q[o].x, f1 = (float)q[o].y;
                const float f2 = (float)q[o].z, f3 = (float)q[o].w;
                qs[o][0] = mul2(pack2(f0, f0), s2);
                qs[o][1] = mul2(pack2(f1, f1), s2);
                qs[o][2] = mul2(pack2(f2, f2), s2);
                qs[o][3] = mul2(pack2(f3, f3), s2);
            }
        }

        // math: 4 k x 4 outputs x 4 batch-pairs = 64 fma2
        #pragma unroll
        for (int k = 0; k < 4; ++k)
            #pragma unroll
            for (int o = 0; o < OPW; ++o) {
                acc[o][0] = fma2(xp[k][0], qs[o][k], acc[o][0]);
                acc[o][1] = fma2(xp[k][1], qs[o][k], acc[o][1]);
                acc[o][2] = fma2(xp[k][2], qs[o][k], acc[o][2]);
                acc[o][3] = fma2(xp[k][3], qs[o][k], acc[o][3]);
            }
    }

    // ---- unpack batch-pairs (no lo+hi add needed), butterfly across lanes ----
    float r[OPW][BATCH];
    #pragma unroll
    for (int o = 0; o < OPW; ++o)
        #pragma unroll
        for (int bp = 0; bp < 4; ++bp)
            unpack2(acc[o][bp], r[o][2 * bp], r[o][2 * bp + 1]);
    #pragma unroll
    for (int off = 16; off > 0; off >>= 1)
        #pragma unroll
        for (int o = 0; o < OPW; ++o)
            #pragma unroll
            for (int b = 0; b < BATCH; ++b)
                r[o][b] += __shfl_xor_sync(0xffffffffu, r[o][b], off);

    if (lane == 0) {
        #pragma unroll
        for (int o = 0; o < OPW; ++o)
            #pragma unroll
            for (int b = 0; b < BATCH; ++b)
                bounce[o * BATCH + b] = r[o][b];
    }
    __syncwarp();

    // 32 results, one per lane; fold in zero/offset term
    const int o = lane >> 3, b = lane & 7;
    const int n = n0 + o;
    float offt = 0.f;
    #pragma unroll
    for (int g2 = 0; g2 < NG; ++g2) {
        float s = __ldg(sc + g2 * OUT_F + n);
        float z = __ldg(zr + g2 * OUT_F + n);
        offt = fmaf(z - 8.f * s, g_sx[b * NG + g2], offt);
    }
    out[b * OUT_F + n] = bounce[lane] + offt;
}

extern "C" void kernel_launch(void* const* d_in, const int* in_sizes, int n_in,
                              void* d_out, int out_size) {
    const float* x  = (const float*)d_in[0];
    const int*   qw = (const int*)d_in[1];
    const float* sc = (const float*)d_in[2];
    const float* zr = (const float*)d_in[3];
    float* out = (float*)d_out;

    prep_kernel<<<32, 256>>>(x);
    w4a32_main<<<OUT_F / OPW, TPB>>>(qw, sc, zr, out);   // 3072 x 32
}